// round 4
// baseline (speedup 1.0000x reference)
#include <cuda_runtime.h>
#include <cuda_bf16.h>
#include <cstdint>

// ================================================================
// AutoGNN, fused pipeline (4 launches):
//   1) split_w:     W1/W2/WL -> bf16 hi/lo (WL padded 40->64 rows)
//   2) gemm_first:  Y1 = X @ W1^T        (fp32 X split in-register)
//   3) fused g+g:   Y2 = relu(mean(Y1[nbrs])) @ W2^T
//   4) fused g+g:   out = relu(mean(Y2[nbrs])) @ WL^T
// GEMMs: mma.sync m16n8k16 bf16, 3-term hi/lo split, fp32 accum.
// ================================================================

#define FEAT 128
#define SAMPLE 25
#define CLASSES 40
#define MAXN 100000
#define RS 272   // smem row stride bytes (136 bf16): conflict-free ldmatrix

__device__ float g_Y1[(size_t)MAXN * FEAT];
__device__ float g_Y2[(size_t)MAXN * FEAT];
__device__ __nv_bfloat16 g_W1hi[128 * 128], g_W1lo[128 * 128];
__device__ __nv_bfloat16 g_W2hi[128 * 128], g_W2lo[128 * 128];
__device__ __nv_bfloat16 g_WLhi[64 * 128],  g_WLlo[64 * 128];

__device__ __forceinline__ uint32_t smem_u32(const void* p) {
    uint32_t a;
    asm("{ .reg .u64 t; cvta.to.shared.u64 t, %1; cvt.u32.u64 %0, t; }" : "=r"(a) : "l"(p));
    return a;
}
__device__ __forceinline__ void ldsm4(uint32_t addr, uint32_t& r0, uint32_t& r1,
                                      uint32_t& r2, uint32_t& r3) {
    asm volatile("ldmatrix.sync.aligned.m8n8.x4.shared.b16 {%0,%1,%2,%3}, [%4];"
                 : "=r"(r0), "=r"(r1), "=r"(r2), "=r"(r3) : "r"(addr));
}
__device__ __forceinline__ void mma_bf16(float* c, const uint32_t* a,
                                         uint32_t b0, uint32_t b1) {
    asm volatile(
        "mma.sync.aligned.m16n8k16.row.col.f32.bf16.bf16.f32 "
        "{%0,%1,%2,%3}, {%4,%5,%6,%7}, {%8,%9}, {%0,%1,%2,%3};"
        : "+f"(c[0]), "+f"(c[1]), "+f"(c[2]), "+f"(c[3])
        : "r"(a[0]), "r"(a[1]), "r"(a[2]), "r"(a[3]), "r"(b0), "r"(b1));
}

// ---------------- shared MMA core (16 warps, CTA tile 128 x NOUT) -----------
// smem layout: [Ahi 128*RS][Alo 128*RS][Whi NOUT*RS][Wlo NOUT*RS]
template<int NOUT, int CST>
__device__ __forceinline__ void mma_core_and_store(
    char* smem, float* __restrict__ C, int m0, int n)
{
    constexpr int OFF_ALO = 128 * RS;
    constexpr int OFF_WHI = 2 * 128 * RS;
    constexpr int OFF_WLO = OFF_WHI + NOUT * RS;
    constexpr int WN = NOUT / 4;       // warp n-extent (32 or 16)
    constexpr int NT = WN / 8;         // n8 tiles per warp (4 or 2)

    const int tid  = threadIdx.x;
    const int wid  = tid >> 5;
    const int lane = tid & 31;
    const int wm   = wid >> 2;         // 0..3 -> m offset wm*32
    const int wn   = wid & 3;          // 0..3 -> n offset wn*WN

    const uint32_t sb = smem_u32(smem);
    const uint32_t aBase[3] = { sb, sb, sb + OFF_ALO };
    const uint32_t wBase[3] = { sb + OFF_WHI, sb + OFF_WLO, sb + OFF_WHI };

    const int l15   = lane & 15;
    const int aHalf = (lane & 16) ? 16 : 0;
    const uint32_t aRow0 = (uint32_t)((wm * 32 + l15) * RS + aHalf);
    const uint32_t aRow1 = aRow0 + 16 * RS;
    const int bRow  = (lane & 7) + ((lane & 16) ? 8 : 0);
    const int bHalf = (lane & 8) ? 16 : 0;
    uint32_t bRowByte[NT / 2 > 0 ? NT / 2 : 1];
    #pragma unroll
    for (int jp = 0; jp < NT / 2; jp++)
        bRowByte[jp] = (uint32_t)((wn * WN + jp * 16 + bRow) * RS + bHalf);

    float c[2][NT][4];
    #pragma unroll
    for (int mt = 0; mt < 2; mt++)
        #pragma unroll
        for (int j = 0; j < NT; j++)
            #pragma unroll
            for (int q = 0; q < 4; q++) c[mt][j][q] = 0.f;

    #pragma unroll
    for (int s = 0; s < 3; s++) {
        #pragma unroll
        for (int ks = 0; ks < 8; ks++) {
            const uint32_t kb = ks * 32;
            uint32_t a[2][4];
            ldsm4(aBase[s] + aRow0 + kb, a[0][0], a[0][1], a[0][2], a[0][3]);
            ldsm4(aBase[s] + aRow1 + kb, a[1][0], a[1][1], a[1][2], a[1][3]);
            uint32_t b[NT][2];
            #pragma unroll
            for (int jp = 0; jp < NT / 2; jp++)
                ldsm4(wBase[s] + bRowByte[jp] + kb,
                      b[2 * jp][0], b[2 * jp][1], b[2 * jp + 1][0], b[2 * jp + 1][1]);
            #pragma unroll
            for (int mt = 0; mt < 2; mt++)
                #pragma unroll
                for (int j = 0; j < NT; j++)
                    mma_bf16(c[mt][j], a[mt], b[j][0], b[j][1]);
        }
    }

    const int qrow = lane >> 2;
    const int qcol = (lane & 3) * 2;
    #pragma unroll
    for (int mt = 0; mt < 2; mt++) {
        #pragma unroll
        for (int half = 0; half < 2; half++) {
            int m_g = m0 + wm * 32 + mt * 16 + qrow + half * 8;
            if (m_g < n) {
                float* crow = C + (size_t)m_g * CST;
                #pragma unroll
                for (int j = 0; j < NT; j++) {
                    int n_g = wn * WN + j * 8 + qcol;
                    if (CST == 128 || n_g < CST) {
                        float2 v = make_float2(c[mt][j][half * 2], c[mt][j][half * 2 + 1]);
                        *reinterpret_cast<float2*>(crow + n_g) = v;
                    }
                }
            }
        }
    }
}

// W tile loader: NOUT rows x 128 bf16 (hi+lo) into smem
template<int NOUT>
__device__ __forceinline__ void load_w_tiles(
    char* smem, const __nv_bfloat16* __restrict__ Whi,
    const __nv_bfloat16* __restrict__ Wlo)
{
    constexpr int OFF_WHI = 2 * 128 * RS;
    constexpr int OFF_WLO = OFF_WHI + NOUT * RS;
    const int tid = threadIdx.x;
    #pragma unroll
    for (int i = 0; i < NOUT / 32; i++) {
        int t = i * 512 + tid;
        int row = t >> 4;
        int c16 = t & 15;
        size_t g = (size_t)row * 128 + c16 * 8;
        int off = row * RS + c16 * 16;
        *reinterpret_cast<uint4*>(smem + OFF_WHI + off) =
            *reinterpret_cast<const uint4*>(Whi + g);
        *reinterpret_cast<uint4*>(smem + OFF_WLO + off) =
            *reinterpret_cast<const uint4*>(Wlo + g);
    }
}

// ---------------- kernel 2: Y1 = X @ W1^T (X split in-register) ------------
__global__ __launch_bounds__(512, 1) void gemm_first_kernel(
    const float* __restrict__ X,
    const __nv_bfloat16* __restrict__ Whi, const __nv_bfloat16* __restrict__ Wlo,
    float* __restrict__ C, int n)
{
    extern __shared__ char smem[];
    constexpr int OFF_ALO = 128 * RS;
    const int tid = threadIdx.x;
    const int m0  = blockIdx.x * 128;

    // A: 128 rows x 32 float4 = 4096 / 512 threads = 8 each
    #pragma unroll
    for (int i = 0; i < 8; i++) {
        int t = i * 512 + tid;
        int row = t >> 5;
        int c4  = t & 31;
        int grow = m0 + row;
        float4 v = make_float4(0.f, 0.f, 0.f, 0.f);
        if (grow < n)
            v = __ldg(reinterpret_cast<const float4*>(X + (size_t)grow * 128) + c4);
        float f[4] = { v.x, v.y, v.z, v.w };
        __nv_bfloat16 h[4], l[4];
        #pragma unroll
        for (int q = 0; q < 4; q++) {
            h[q] = __float2bfloat16(f[q]);
            l[q] = __float2bfloat16(f[q] - __bfloat162float(h[q]));
        }
        int off = row * RS + c4 * 8;
        *reinterpret_cast<uint2*>(smem + off)           = *reinterpret_cast<uint2*>(h);
        *reinterpret_cast<uint2*>(smem + OFF_ALO + off) = *reinterpret_cast<uint2*>(l);
    }
    load_w_tiles<128>(smem, Whi, Wlo);
    __syncthreads();
    mma_core_and_store<128, 128>(smem, C, m0, n);
}

// ---------------- kernels 3/4: fused gather + GEMM -------------------------
// h = relu(mean(Y[nbrs]))  (warp per node, 8 nodes/warp) -> smem hi/lo tiles
// then C[128, CST] = h @ W^T
template<int NOUT, int CST>
__global__ __launch_bounds__(512, 1) void fused_gather_gemm_kernel(
    const float* __restrict__ Y, const int* __restrict__ nbrs,
    const __nv_bfloat16* __restrict__ Whi, const __nv_bfloat16* __restrict__ Wlo,
    float* __restrict__ C, int n)
{
    extern __shared__ char smem[];
    constexpr int OFF_ALO = 128 * RS;
    const int tid  = threadIdx.x;
    const int wid  = tid >> 5;
    const int lane = tid & 31;
    const int m0   = blockIdx.x * 128;

    load_w_tiles<NOUT>(smem, Whi, Wlo);

    #pragma unroll
    for (int i = 0; i < 8; i++) {
        const int local = wid * 8 + i;
        const int node  = m0 + local;
        float o[4] = { 0.f, 0.f, 0.f, 0.f };
        if (node < n) {
            int idx = 0;
            if (lane < SAMPLE) idx = nbrs[(size_t)node * SAMPLE + lane];
            float4 acc = make_float4(0.f, 0.f, 0.f, 0.f);
            #pragma unroll
            for (int j = 0; j < SAMPLE; j++) {
                int row = __shfl_sync(0xffffffffu, idx, j);
                float4 v = __ldg(reinterpret_cast<const float4*>(Y + (size_t)row * 128) + lane);
                acc.x += v.x; acc.y += v.y; acc.z += v.z; acc.w += v.w;
            }
            const float s = 1.0f / (float)SAMPLE;
            o[0] = fmaxf(acc.x * s, 0.f);
            o[1] = fmaxf(acc.y * s, 0.f);
            o[2] = fmaxf(acc.z * s, 0.f);
            o[3] = fmaxf(acc.w * s, 0.f);
        }
        __nv_bfloat16 h[4], l[4];
        #pragma unroll
        for (int q = 0; q < 4; q++) {
            h[q] = __float2bfloat16(o[q]);
            l[q] = __float2bfloat16(o[q] - __bfloat162float(h[q]));
        }
        int off = local * RS + lane * 8;
        *reinterpret_cast<uint2*>(smem + off)           = *reinterpret_cast<uint2*>(h);
        *reinterpret_cast<uint2*>(smem + OFF_ALO + off) = *reinterpret_cast<uint2*>(l);
    }
    __syncthreads();
    mma_core_and_store<NOUT, CST>(smem, C, m0, n);
}

// ---------------- kernel 1: weight splitter --------------------------------
__global__ void split_w_kernel(const float* __restrict__ W1,
                               const float* __restrict__ W2,
                               const float* __restrict__ WL,
                               __nv_bfloat16* w1h, __nv_bfloat16* w1l,
                               __nv_bfloat16* w2h, __nv_bfloat16* w2l,
                               __nv_bfloat16* wlh, __nv_bfloat16* wll)
{
    int i = blockIdx.x * blockDim.x + threadIdx.x;  // 0 .. 40959
    float v; __nv_bfloat16 *ph, *pl; int idx;
    if (i < 16384)      { v = W1[i];            ph = w1h; pl = w1l; idx = i; }
    else if (i < 32768) { idx = i - 16384; v = W2[idx]; ph = w2h; pl = w2l; }
    else if (i < 40960) {
        idx = i - 32768;                 // 0..8191 over padded [64][128]
        int row = idx >> 7;
        v = (row < CLASSES) ? WL[idx] : 0.f;
        ph = wlh; pl = wll;
    } else return;
    __nv_bfloat16 h = __float2bfloat16(v);
    ph[idx] = h;
    pl[idx] = __float2bfloat16(v - __bfloat162float(h));
}

// ================================================================
extern "C" void kernel_launch(void* const* d_in, const int* in_sizes, int n_in,
                              void* d_out, int out_size)
{
    const float* X    = (const float*)d_in[0];
    const int*   nbrs = (const int*)  d_in[1];
    const float* W1   = (const float*)d_in[2];
    const float* W2   = (const float*)d_in[3];
    const float* WL   = (const float*)d_in[4];
    float*       out  = (float*)d_out;
    const int n = in_sizes[1] / SAMPLE;

    float *Y1, *Y2;
    __nv_bfloat16 *w1h, *w1l, *w2h, *w2l, *wlh, *wll;
    cudaGetSymbolAddress((void**)&Y1,  g_Y1);
    cudaGetSymbolAddress((void**)&Y2,  g_Y2);
    cudaGetSymbolAddress((void**)&w1h, g_W1hi);
    cudaGetSymbolAddress((void**)&w1l, g_W1lo);
    cudaGetSymbolAddress((void**)&w2h, g_W2hi);
    cudaGetSymbolAddress((void**)&w2l, g_W2lo);
    cudaGetSymbolAddress((void**)&wlh, g_WLhi);
    cudaGetSymbolAddress((void**)&wll, g_WLlo);

    const int SM128 = RS * (2 * 128 + 2 * 128);   // 139264
    const int SM64  = RS * (2 * 128 + 2 * 64);    // 104448
    cudaFuncSetAttribute(gemm_first_kernel,
                         cudaFuncAttributeMaxDynamicSharedMemorySize, SM128);
    cudaFuncSetAttribute(fused_gather_gemm_kernel<128, 128>,
                         cudaFuncAttributeMaxDynamicSharedMemorySize, SM128);
    cudaFuncSetAttribute(fused_gather_gemm_kernel<64, 40>,
                         cudaFuncAttributeMaxDynamicSharedMemorySize, SM64);

    const int gg = (n + 127) / 128;

    split_w_kernel<<<160, 256>>>(W1, W2, WL, w1h, w1l, w2h, w2l, wlh, wll);
    gemm_first_kernel<<<gg, 512, SM128>>>(X, w1h, w1l, Y1, n);
    fused_gather_gemm_kernel<128, 128><<<gg, 512, SM128>>>(Y1, nbrs, w2h, w2l, Y2, n);
    fused_gather_gemm_kernel<64, 40><<<gg, 512, SM64>>>(Y2, nbrs, wlh, wll, out, n);
}

// round 5
// speedup vs baseline: 1.0288x; 1.0288x over previous
#include <cuda_runtime.h>
#include <cuda_bf16.h>
#include <cstdint>

// ================================================================
// AutoGNN, 6 launches — each phase at its own roofline:
//   1) split_w:    W1/W2/WL -> bf16 hi/lo (WL padded 40->64 rows)
//   2) gemm_first: Y = X @ W1^T   (fp32 X, in-register hi/lo split)
//   3) gather:     (Ahi,Alo) = split(relu(mean(Y[nbrs])))   [high occ]
//   4) gemm_mid:   Y = (Ahi+Alo) @ W2^T                     [16 warps]
//   5) gather
//   6) gemm_mid<64,40>: out = (Ahi+Alo) @ WL^T
// GEMMs: mma.sync m16n8k16 bf16, 3-term hi/lo split, fp32 accum.
// ================================================================

#define FEAT 128
#define SAMPLE 25
#define CLASSES 40
#define MAXN 100000
#define RS 272   // smem row stride bytes (136 bf16): conflict-free ldmatrix

__device__ float         g_Y  [(size_t)MAXN * FEAT];
__device__ __nv_bfloat16 g_Ahi[(size_t)MAXN * FEAT];
__device__ __nv_bfloat16 g_Alo[(size_t)MAXN * FEAT];
__device__ __nv_bfloat16 g_W1hi[128 * 128], g_W1lo[128 * 128];
__device__ __nv_bfloat16 g_W2hi[128 * 128], g_W2lo[128 * 128];
__device__ __nv_bfloat16 g_WLhi[64 * 128],  g_WLlo[64 * 128];

__device__ __forceinline__ uint32_t smem_u32(const void* p) {
    uint32_t a;
    asm("{ .reg .u64 t; cvta.to.shared.u64 t, %1; cvt.u32.u64 %0, t; }" : "=r"(a) : "l"(p));
    return a;
}
__device__ __forceinline__ void ldsm4(uint32_t addr, uint32_t& r0, uint32_t& r1,
                                      uint32_t& r2, uint32_t& r3) {
    asm volatile("ldmatrix.sync.aligned.m8n8.x4.shared.b16 {%0,%1,%2,%3}, [%4];"
                 : "=r"(r0), "=r"(r1), "=r"(r2), "=r"(r3) : "r"(addr));
}
__device__ __forceinline__ void mma_bf16(float* c, const uint32_t* a,
                                         uint32_t b0, uint32_t b1) {
    asm volatile(
        "mma.sync.aligned.m16n8k16.row.col.f32.bf16.bf16.f32 "
        "{%0,%1,%2,%3}, {%4,%5,%6,%7}, {%8,%9}, {%0,%1,%2,%3};"
        : "+f"(c[0]), "+f"(c[1]), "+f"(c[2]), "+f"(c[3])
        : "r"(a[0]), "r"(a[1]), "r"(a[2]), "r"(a[3]), "r"(b0), "r"(b1));
}

// ---------------- MMA core: 16 warps, CTA tile 128 x NOUT -------------------
// smem: [Ahi 128*RS][Alo 128*RS][Whi NOUT*RS][Wlo NOUT*RS]
template<int NOUT, int CST>
__device__ __forceinline__ void mma_core_and_store(
    char* smem, float* __restrict__ C, int m0, int n)
{
    constexpr int OFF_ALO = 128 * RS;
    constexpr int OFF_WHI = 2 * 128 * RS;
    constexpr int OFF_WLO = OFF_WHI + NOUT * RS;
    constexpr int WN = NOUT / 4;       // warp n-extent (32 or 16)
    constexpr int NT = WN / 8;         // n8 tiles per warp (4 or 2)

    const int tid  = threadIdx.x;
    const int wid  = tid >> 5;
    const int lane = tid & 31;
    const int wm   = wid >> 2;         // 0..3 -> m offset wm*32
    const int wn   = wid & 3;          // 0..3 -> n offset wn*WN

    const uint32_t sb = smem_u32(smem);
    const uint32_t aBase[3] = { sb, sb, sb + OFF_ALO };
    const uint32_t wBase[3] = { sb + OFF_WHI, sb + OFF_WLO, sb + OFF_WHI };

    const int l15   = lane & 15;
    const int aHalf = (lane & 16) ? 16 : 0;
    const uint32_t aRow0 = (uint32_t)((wm * 32 + l15) * RS + aHalf);
    const uint32_t aRow1 = aRow0 + 16 * RS;
    const int bRow  = (lane & 7) + ((lane & 16) ? 8 : 0);
    const int bHalf = (lane & 8) ? 16 : 0;
    uint32_t bRowByte[NT / 2];
    #pragma unroll
    for (int jp = 0; jp < NT / 2; jp++)
        bRowByte[jp] = (uint32_t)((wn * WN + jp * 16 + bRow) * RS + bHalf);

    float c[2][NT][4];
    #pragma unroll
    for (int mt = 0; mt < 2; mt++)
        #pragma unroll
        for (int j = 0; j < NT; j++)
            #pragma unroll
            for (int q = 0; q < 4; q++) c[mt][j][q] = 0.f;

    #pragma unroll
    for (int s = 0; s < 3; s++) {
        #pragma unroll
        for (int ks = 0; ks < 8; ks++) {
            const uint32_t kb = ks * 32;
            uint32_t a[2][4];
            ldsm4(aBase[s] + aRow0 + kb, a[0][0], a[0][1], a[0][2], a[0][3]);
            ldsm4(aBase[s] + aRow1 + kb, a[1][0], a[1][1], a[1][2], a[1][3]);
            uint32_t b[NT][2];
            #pragma unroll
            for (int jp = 0; jp < NT / 2; jp++)
                ldsm4(wBase[s] + bRowByte[jp] + kb,
                      b[2 * jp][0], b[2 * jp][1], b[2 * jp + 1][0], b[2 * jp + 1][1]);
            #pragma unroll
            for (int mt = 0; mt < 2; mt++)
                #pragma unroll
                for (int j = 0; j < NT; j++)
                    mma_bf16(c[mt][j], a[mt], b[j][0], b[j][1]);
        }
    }

    const int qrow = lane >> 2;
    const int qcol = (lane & 3) * 2;
    #pragma unroll
    for (int mt = 0; mt < 2; mt++) {
        #pragma unroll
        for (int half = 0; half < 2; half++) {
            int m_g = m0 + wm * 32 + mt * 16 + qrow + half * 8;
            if (m_g < n) {
                float* crow = C + (size_t)m_g * CST;
                #pragma unroll
                for (int j = 0; j < NT; j++) {
                    int n_g = wn * WN + j * 8 + qcol;
                    if (CST == 128 || n_g < CST) {
                        float2 v = make_float2(c[mt][j][half * 2], c[mt][j][half * 2 + 1]);
                        *reinterpret_cast<float2*>(crow + n_g) = v;
                    }
                }
            }
        }
    }
}

// W tile loader: NOUT rows x 128 bf16 (hi+lo) into smem (512 threads)
template<int NOUT>
__device__ __forceinline__ void load_w_tiles(
    char* smem, const __nv_bfloat16* __restrict__ Whi,
    const __nv_bfloat16* __restrict__ Wlo)
{
    constexpr int OFF_WHI = 2 * 128 * RS;
    constexpr int OFF_WLO = OFF_WHI + NOUT * RS;
    const int tid = threadIdx.x;
    #pragma unroll
    for (int i = 0; i < NOUT / 32; i++) {
        int t = i * 512 + tid;
        int row = t >> 4;
        int c16 = t & 15;
        size_t g = (size_t)row * 128 + c16 * 8;
        int off = row * RS + c16 * 16;
        *reinterpret_cast<uint4*>(smem + OFF_WHI + off) =
            *reinterpret_cast<const uint4*>(Whi + g);
        *reinterpret_cast<uint4*>(smem + OFF_WLO + off) =
            *reinterpret_cast<const uint4*>(Wlo + g);
    }
}

// ---------------- kernel 2: Y = X @ W1^T (fp32 X split in-register) --------
__global__ __launch_bounds__(512, 1) void gemm_first_kernel(
    const float* __restrict__ X,
    const __nv_bfloat16* __restrict__ Whi, const __nv_bfloat16* __restrict__ Wlo,
    float* __restrict__ C, int n)
{
    extern __shared__ char smem[];
    constexpr int OFF_ALO = 128 * RS;
    const int tid = threadIdx.x;
    const int m0  = blockIdx.x * 128;

    #pragma unroll
    for (int i = 0; i < 8; i++) {
        int t = i * 512 + tid;              // 4096 float4
        int row = t >> 5;
        int c4  = t & 31;
        int grow = m0 + row;
        float4 v = make_float4(0.f, 0.f, 0.f, 0.f);
        if (grow < n)
            v = __ldg(reinterpret_cast<const float4*>(X + (size_t)grow * 128) + c4);
        float f[4] = { v.x, v.y, v.z, v.w };
        __nv_bfloat16 h[4], l[4];
        #pragma unroll
        for (int q = 0; q < 4; q++) {
            h[q] = __float2bfloat16(f[q]);
            l[q] = __float2bfloat16(f[q] - __bfloat162float(h[q]));
        }
        int off = row * RS + c4 * 8;
        *reinterpret_cast<uint2*>(smem + off)           = *reinterpret_cast<uint2*>(h);
        *reinterpret_cast<uint2*>(smem + OFF_ALO + off) = *reinterpret_cast<uint2*>(l);
    }
    load_w_tiles<128>(smem, Whi, Wlo);
    __syncthreads();
    mma_core_and_store<128, 128>(smem, C, m0, n);
}

// ---------------- kernels 4/6: (Ahi+Alo) @ W^T ------------------------------
template<int NOUT, int CST>
__global__ __launch_bounds__(512, 1) void gemm_mid_kernel(
    const __nv_bfloat16* __restrict__ Ahi, const __nv_bfloat16* __restrict__ Alo,
    const __nv_bfloat16* __restrict__ Whi, const __nv_bfloat16* __restrict__ Wlo,
    float* __restrict__ C, int n)
{
    extern __shared__ char smem[];
    constexpr int OFF_ALO = 128 * RS;
    const int tid = threadIdx.x;
    const int m0  = blockIdx.x * 128;

    #pragma unroll
    for (int i = 0; i < 4; i++) {
        int t = i * 512 + tid;              // 2048 uint4
        int row = t >> 4;
        int c16 = t & 15;
        int grow = m0 + row;
        uint4 vh = make_uint4(0, 0, 0, 0), vl = make_uint4(0, 0, 0, 0);
        if (grow < n) {
            size_t g = (size_t)grow * 128 + c16 * 8;
            vh = *reinterpret_cast<const uint4*>(Ahi + g);
            vl = *reinterpret_cast<const uint4*>(Alo + g);
        }
        int off = row * RS + c16 * 16;
        *reinterpret_cast<uint4*>(smem + off)           = vh;
        *reinterpret_cast<uint4*>(smem + OFF_ALO + off) = vl;
    }
    load_w_tiles<NOUT>(smem, Whi, Wlo);
    __syncthreads();
    mma_core_and_store<NOUT, CST>(smem, C, m0, n);
}

// ---------------- kernels 3/5: gather + split (high occupancy) --------------
__global__ __launch_bounds__(256) void gather_split_kernel(
    const float* __restrict__ Y, const int* __restrict__ nbrs,
    __nv_bfloat16* __restrict__ Hhi, __nv_bfloat16* __restrict__ Hlo, int n)
{
    const int warp = (blockIdx.x * blockDim.x + threadIdx.x) >> 5;
    const int lane = threadIdx.x & 31;
    if (warp >= n) return;

    int idx = 0;
    if (lane < SAMPLE) idx = nbrs[(size_t)warp * SAMPLE + lane];

    float4 acc = make_float4(0.f, 0.f, 0.f, 0.f);
    #pragma unroll
    for (int j = 0; j < SAMPLE; j++) {
        int row = __shfl_sync(0xffffffffu, idx, j);
        float4 v = __ldg(reinterpret_cast<const float4*>(Y + (size_t)row * 128) + lane);
        acc.x += v.x; acc.y += v.y; acc.z += v.z; acc.w += v.w;
    }
    const float s = 1.0f / (float)SAMPLE;
    float o[4] = { fmaxf(acc.x * s, 0.f), fmaxf(acc.y * s, 0.f),
                   fmaxf(acc.z * s, 0.f), fmaxf(acc.w * s, 0.f) };
    __nv_bfloat16 h[4], l[4];
    #pragma unroll
    for (int q = 0; q < 4; q++) {
        h[q] = __float2bfloat16(o[q]);
        l[q] = __float2bfloat16(o[q] - __bfloat162float(h[q]));
    }
    *(reinterpret_cast<uint2*>(Hhi + (size_t)warp * 128) + lane) =
        *reinterpret_cast<uint2*>(h);
    *(reinterpret_cast<uint2*>(Hlo + (size_t)warp * 128) + lane) =
        *reinterpret_cast<uint2*>(l);
}

// ---------------- kernel 1: weight splitter --------------------------------
__global__ void split_w_kernel(const float* __restrict__ W1,
                               const float* __restrict__ W2,
                               const float* __restrict__ WL,
                               __nv_bfloat16* w1h, __nv_bfloat16* w1l,
                               __nv_bfloat16* w2h, __nv_bfloat16* w2l,
                               __nv_bfloat16* wlh, __nv_bfloat16* wll)
{
    int i = blockIdx.x * blockDim.x + threadIdx.x;  // 0 .. 40959
    float v; __nv_bfloat16 *ph, *pl; int idx;
    if (i < 16384)      { v = W1[i];            ph = w1h; pl = w1l; idx = i; }
    else if (i < 32768) { idx = i - 16384; v = W2[idx]; ph = w2h; pl = w2l; }
    else if (i < 40960) {
        idx = i - 32768;                 // padded [64][128]
        int row = idx >> 7;
        v = (row < CLASSES) ? WL[idx] : 0.f;
        ph = wlh; pl = wll;
    } else return;
    __nv_bfloat16 h = __float2bfloat16(v);
    ph[idx] = h;
    pl[idx] = __float2bfloat16(v - __bfloat162float(h));
}

// ================================================================
extern "C" void kernel_launch(void* const* d_in, const int* in_sizes, int n_in,
                              void* d_out, int out_size)
{
    const float* X    = (const float*)d_in[0];
    const int*   nbrs = (const int*)  d_in[1];
    const float* W1   = (const float*)d_in[2];
    const float* W2   = (const float*)d_in[3];
    const float* WL   = (const float*)d_in[4];
    float*       out  = (float*)d_out;
    const int n = in_sizes[1] / SAMPLE;

    float* Y;
    __nv_bfloat16 *Ahi, *Alo, *w1h, *w1l, *w2h, *w2l, *wlh, *wll;
    cudaGetSymbolAddress((void**)&Y,   g_Y);
    cudaGetSymbolAddress((void**)&Ahi, g_Ahi);
    cudaGetSymbolAddress((void**)&Alo, g_Alo);
    cudaGetSymbolAddress((void**)&w1h, g_W1hi);
    cudaGetSymbolAddress((void**)&w1l, g_W1lo);
    cudaGetSymbolAddress((void**)&w2h, g_W2hi);
    cudaGetSymbolAddress((void**)&w2l, g_W2lo);
    cudaGetSymbolAddress((void**)&wlh, g_WLhi);
    cudaGetSymbolAddress((void**)&wll, g_WLlo);

    const int SM128 = RS * (2 * 128 + 2 * 128);   // 139264
    const int SM64  = RS * (2 * 128 + 2 * 64);    // 104448
    cudaFuncSetAttribute(gemm_first_kernel,
                         cudaFuncAttributeMaxDynamicSharedMemorySize, SM128);
    cudaFuncSetAttribute(gemm_mid_kernel<128, 128>,
                         cudaFuncAttributeMaxDynamicSharedMemorySize, SM128);
    cudaFuncSetAttribute(gemm_mid_kernel<64, 40>,
                         cudaFuncAttributeMaxDynamicSharedMemorySize, SM64);

    const int gg = (n + 127) / 128;
    const int ag = (n + 7) / 8;

    split_w_kernel<<<160, 256>>>(W1, W2, WL, w1h, w1l, w2h, w2l, wlh, wll);
    gemm_first_kernel<<<gg, 512, SM128>>>(X, w1h, w1l, Y, n);
    gather_split_kernel<<<ag, 256>>>(Y, nbrs, Ahi, Alo, n);
    gemm_mid_kernel<128, 128><<<gg, 512, SM128>>>(Ahi, Alo, w2h, w2l, Y, n);
    gather_split_kernel<<<ag, 256>>>(Y, nbrs, Ahi, Alo, n);
    gemm_mid_kernel<64, 40><<<gg, 512, SM64>>>(Ahi, Alo, wlh, wll, out, n);
}

// round 6
// speedup vs baseline: 1.0314x; 1.0025x over previous
#include <cuda_runtime.h>
#include <cuda_bf16.h>
#include <cstdint>

// ================================================================
// AutoGNN, 6 launches:
//   1) split_w:    W1/W2/WL -> bf16 hi/lo (WL padded 40->64 rows)
//   2) gemm_first: Y = X @ W1^T   (fp32 X, in-register hi/lo split)
//   3) gather:     (Ahi,Alo) = split(relu(mean(Y[nbrs])))
//   4) gemm_mid:   Y = (Ahi+Alo) @ W2^T
//   5) gather
//   6) gemm_mid<64,40>: out = (Ahi+Alo) @ WL^T
// GEMM CTA tile M=64 (smem 102KB) -> 2 CTAs/SM: load/MMA overlap.
// mma.sync m16n8k16 bf16, 3-term hi/lo split, fp32 accum.
// ================================================================

#define FEAT 128
#define SAMPLE 25
#define CLASSES 40
#define MAXN 100000
#define RS 272   // smem row stride bytes (136 bf16): conflict-free ldmatrix

__device__ float         g_Y  [(size_t)MAXN * FEAT];
__device__ __nv_bfloat16 g_Ahi[(size_t)MAXN * FEAT];
__device__ __nv_bfloat16 g_Alo[(size_t)MAXN * FEAT];
__device__ __nv_bfloat16 g_W1hi[128 * 128], g_W1lo[128 * 128];
__device__ __nv_bfloat16 g_W2hi[128 * 128], g_W2lo[128 * 128];
__device__ __nv_bfloat16 g_WLhi[64 * 128],  g_WLlo[64 * 128];

__device__ __forceinline__ uint32_t smem_u32(const void* p) {
    uint32_t a;
    asm("{ .reg .u64 t; cvta.to.shared.u64 t, %1; cvt.u32.u64 %0, t; }" : "=r"(a) : "l"(p));
    return a;
}
__device__ __forceinline__ void ldsm4(uint32_t addr, uint32_t& r0, uint32_t& r1,
                                      uint32_t& r2, uint32_t& r3) {
    asm volatile("ldmatrix.sync.aligned.m8n8.x4.shared.b16 {%0,%1,%2,%3}, [%4];"
                 : "=r"(r0), "=r"(r1), "=r"(r2), "=r"(r3) : "r"(addr));
}
__device__ __forceinline__ void mma_bf16(float* c, const uint32_t* a,
                                         uint32_t b0, uint32_t b1) {
    asm volatile(
        "mma.sync.aligned.m16n8k16.row.col.f32.bf16.bf16.f32 "
        "{%0,%1,%2,%3}, {%4,%5,%6,%7}, {%8,%9}, {%0,%1,%2,%3};"
        : "+f"(c[0]), "+f"(c[1]), "+f"(c[2]), "+f"(c[3])
        : "r"(a[0]), "r"(a[1]), "r"(a[2]), "r"(a[3]), "r"(b0), "r"(b1));
}

// ---------------- MMA core: 8 warps, CTA tile 64 x NOUT ---------------------
// smem: [Ahi 64*RS][Alo 64*RS][Whi NOUT*RS][Wlo NOUT*RS]
template<int NOUT, int CST>
__device__ __forceinline__ void mma_core_and_store(
    char* smem, float* __restrict__ C, int m0, int n)
{
    constexpr int OFF_ALO = 64 * RS;
    constexpr int OFF_WHI = 128 * RS;
    constexpr int OFF_WLO = OFF_WHI + NOUT * RS;
    constexpr int WN = NOUT / 4;       // warp n-extent (32 or 16)
    constexpr int NT = WN / 8;         // n8 tiles per warp (4 or 2)

    const int tid  = threadIdx.x;
    const int wid  = tid >> 5;
    const int lane = tid & 31;
    const int wm   = wid >> 2;         // 0..1 -> m offset wm*32
    const int wn   = wid & 3;          // 0..3 -> n offset wn*WN

    const uint32_t sb = smem_u32(smem);
    const uint32_t aBase[3] = { sb, sb, sb + OFF_ALO };
    const uint32_t wBase[3] = { sb + OFF_WHI, sb + OFF_WLO, sb + OFF_WHI };

    const int l15   = lane & 15;
    const int aHalf = (lane & 16) ? 16 : 0;
    const uint32_t aRow0 = (uint32_t)((wm * 32 + l15) * RS + aHalf);
    const uint32_t aRow1 = aRow0 + 16 * RS;
    const int bRow  = (lane & 7) + ((lane & 16) ? 8 : 0);
    const int bHalf = (lane & 8) ? 16 : 0;
    uint32_t bRowByte[NT / 2];
    #pragma unroll
    for (int jp = 0; jp < NT / 2; jp++)
        bRowByte[jp] = (uint32_t)((wn * WN + jp * 16 + bRow) * RS + bHalf);

    float c[2][NT][4];
    #pragma unroll
    for (int mt = 0; mt < 2; mt++)
        #pragma unroll
        for (int j = 0; j < NT; j++)
            #pragma unroll
            for (int q = 0; q < 4; q++) c[mt][j][q] = 0.f;

    #pragma unroll
    for (int s = 0; s < 3; s++) {
        #pragma unroll
        for (int ks = 0; ks < 8; ks++) {
            const uint32_t kb = ks * 32;
            uint32_t a[2][4];
            ldsm4(aBase[s] + aRow0 + kb, a[0][0], a[0][1], a[0][2], a[0][3]);
            ldsm4(aBase[s] + aRow1 + kb, a[1][0], a[1][1], a[1][2], a[1][3]);
            uint32_t b[NT][2];
            #pragma unroll
            for (int jp = 0; jp < NT / 2; jp++)
                ldsm4(wBase[s] + bRowByte[jp] + kb,
                      b[2 * jp][0], b[2 * jp][1], b[2 * jp + 1][0], b[2 * jp + 1][1]);
            #pragma unroll
            for (int mt = 0; mt < 2; mt++)
                #pragma unroll
                for (int j = 0; j < NT; j++)
                    mma_bf16(c[mt][j], a[mt], b[j][0], b[j][1]);
        }
    }

    const int qrow = lane >> 2;
    const int qcol = (lane & 3) * 2;
    #pragma unroll
    for (int mt = 0; mt < 2; mt++) {
        #pragma unroll
        for (int half = 0; half < 2; half++) {
            int m_g = m0 + wm * 32 + mt * 16 + qrow + half * 8;
            if (m_g < n) {
                float* crow = C + (size_t)m_g * CST;
                #pragma unroll
                for (int j = 0; j < NT; j++) {
                    int n_g = wn * WN + j * 8 + qcol;
                    if (CST == 128 || n_g < CST) {
                        float2 v = make_float2(c[mt][j][half * 2], c[mt][j][half * 2 + 1]);
                        *reinterpret_cast<float2*>(crow + n_g) = v;
                    }
                }
            }
        }
    }
}

// W tile loader: NOUT rows x 128 bf16 (hi+lo), 256 threads
template<int NOUT>
__device__ __forceinline__ void load_w_tiles(
    char* smem, const __nv_bfloat16* __restrict__ Whi,
    const __nv_bfloat16* __restrict__ Wlo)
{
    constexpr int OFF_WHI = 128 * RS;
    constexpr int OFF_WLO = OFF_WHI + NOUT * RS;
    const int tid = threadIdx.x;
    #pragma unroll
    for (int i = 0; i < NOUT / 16; i++) {
        int t = i * 256 + tid;
        int row = t >> 4;
        int c16 = t & 15;
        size_t g = (size_t)row * 128 + c16 * 8;
        int off = row * RS + c16 * 16;
        *reinterpret_cast<uint4*>(smem + OFF_WHI + off) =
            *reinterpret_cast<const uint4*>(Whi + g);
        *reinterpret_cast<uint4*>(smem + OFF_WLO + off) =
            *reinterpret_cast<const uint4*>(Wlo + g);
    }
}

// ---------------- kernel 2: Y = X @ W1^T (fp32 X split in-register) --------
__global__ __launch_bounds__(256, 2) void gemm_first_kernel(
    const float* __restrict__ X,
    const __nv_bfloat16* __restrict__ Whi, const __nv_bfloat16* __restrict__ Wlo,
    float* __restrict__ C, int n)
{
    extern __shared__ char smem[];
    constexpr int OFF_ALO = 64 * RS;
    const int tid = threadIdx.x;
    const int m0  = blockIdx.x * 64;

    #pragma unroll
    for (int i = 0; i < 8; i++) {
        int t = i * 256 + tid;              // 2048 float4
        int row = t >> 5;
        int c4  = t & 31;
        int grow = m0 + row;
        float4 v = make_float4(0.f, 0.f, 0.f, 0.f);
        if (grow < n)
            v = __ldg(reinterpret_cast<const float4*>(X + (size_t)grow * 128) + c4);
        float f[4] = { v.x, v.y, v.z, v.w };
        __nv_bfloat16 h[4], l[4];
        #pragma unroll
        for (int q = 0; q < 4; q++) {
            h[q] = __float2bfloat16(f[q]);
            l[q] = __float2bfloat16(f[q] - __bfloat162float(h[q]));
        }
        int off = row * RS + c4 * 8;
        *reinterpret_cast<uint2*>(smem + off)           = *reinterpret_cast<uint2*>(h);
        *reinterpret_cast<uint2*>(smem + OFF_ALO + off) = *reinterpret_cast<uint2*>(l);
    }
    load_w_tiles<128>(smem, Whi, Wlo);
    __syncthreads();
    mma_core_and_store<128, 128>(smem, C, m0, n);
}

// ---------------- kernels 4/6: (Ahi+Alo) @ W^T ------------------------------
template<int NOUT, int CST>
__global__ __launch_bounds__(256, 2) void gemm_mid_kernel(
    const __nv_bfloat16* __restrict__ Ahi, const __nv_bfloat16* __restrict__ Alo,
    const __nv_bfloat16* __restrict__ Whi, const __nv_bfloat16* __restrict__ Wlo,
    float* __restrict__ C, int n)
{
    extern __shared__ char smem[];
    constexpr int OFF_ALO = 64 * RS;
    const int tid = threadIdx.x;
    const int m0  = blockIdx.x * 64;

    #pragma unroll
    for (int i = 0; i < 4; i++) {
        int t = i * 256 + tid;              // 1024 uint4 per buffer
        int row = t >> 4;
        int c16 = t & 15;
        int grow = m0 + row;
        uint4 vh = make_uint4(0, 0, 0, 0), vl = make_uint4(0, 0, 0, 0);
        if (grow < n) {
            size_t g = (size_t)grow * 128 + c16 * 8;
            vh = *reinterpret_cast<const uint4*>(Ahi + g);
            vl = *reinterpret_cast<const uint4*>(Alo + g);
        }
        int off = row * RS + c16 * 16;
        *reinterpret_cast<uint4*>(smem + off)           = vh;
        *reinterpret_cast<uint4*>(smem + OFF_ALO + off) = vl;
    }
    load_w_tiles<NOUT>(smem, Whi, Wlo);
    __syncthreads();
    mma_core_and_store<NOUT, CST>(smem, C, m0, n);
}

// ---------------- kernels 3/5: gather + split (high occupancy) --------------
__global__ __launch_bounds__(256) void gather_split_kernel(
    const float* __restrict__ Y, const int* __restrict__ nbrs,
    __nv_bfloat16* __restrict__ Hhi, __nv_bfloat16* __restrict__ Hlo, int n)
{
    const int warp = (blockIdx.x * blockDim.x + threadIdx.x) >> 5;
    const int lane = threadIdx.x & 31;
    if (warp >= n) return;

    int idx = 0;
    if (lane < SAMPLE) idx = nbrs[(size_t)warp * SAMPLE + lane];

    float4 acc = make_float4(0.f, 0.f, 0.f, 0.f);
    #pragma unroll
    for (int j = 0; j < SAMPLE; j++) {
        int row = __shfl_sync(0xffffffffu, idx, j);
        float4 v = __ldg(reinterpret_cast<const float4*>(Y + (size_t)row * 128) + lane);
        acc.x += v.x; acc.y += v.y; acc.z += v.z; acc.w += v.w;
    }
    const float s = 1.0f / (float)SAMPLE;
    float o[4] = { fmaxf(acc.x * s, 0.f), fmaxf(acc.y * s, 0.f),
                   fmaxf(acc.z * s, 0.f), fmaxf(acc.w * s, 0.f) };
    __nv_bfloat16 h[4], l[4];
    #pragma unroll
    for (int q = 0; q < 4; q++) {
        h[q] = __float2bfloat16(o[q]);
        l[q] = __float2bfloat16(o[q] - __bfloat162float(h[q]));
    }
    *(reinterpret_cast<uint2*>(Hhi + (size_t)warp * 128) + lane) =
        *reinterpret_cast<uint2*>(h);
    *(reinterpret_cast<uint2*>(Hlo + (size_t)warp * 128) + lane) =
        *reinterpret_cast<uint2*>(l);
}

// ---------------- kernel 1: weight splitter --------------------------------
__global__ void split_w_kernel(const float* __restrict__ W1,
                               const float* __restrict__ W2,
                               const float* __restrict__ WL,
                               __nv_bfloat16* w1h, __nv_bfloat16* w1l,
                               __nv_bfloat16* w2h, __nv_bfloat16* w2l,
                               __nv_bfloat16* wlh, __nv_bfloat16* wll)
{
    int i = blockIdx.x * blockDim.x + threadIdx.x;  // 0 .. 40959
    float v; __nv_bfloat16 *ph, *pl; int idx;
    if (i < 16384)      { v = W1[i];            ph = w1h; pl = w1l; idx = i; }
    else if (i < 32768) { idx = i - 16384; v = W2[idx]; ph = w2h; pl = w2l; }
    else if (i < 40960) {
        idx = i - 32768;                 // padded [64][128]
        int row = idx >> 7;
        v = (row < CLASSES) ? WL[idx] : 0.f;
        ph = wlh; pl = wll;
    } else return;
    __nv_bfloat16 h = __float2bfloat16(v);
    ph[idx] = h;
    pl[idx] = __float2bfloat16(v - __bfloat162float(h));
}

// ================================================================
extern "C" void kernel_launch(void* const* d_in, const int* in_sizes, int n_in,
                              void* d_out, int out_size)
{
    const float* X    = (const float*)d_in[0];
    const int*   nbrs = (const int*)  d_in[1];
    const float* W1   = (const float*)d_in[2];
    const float* W2   = (const float*)d_in[3];
    const float* WL   = (const float*)d_in[4];
    float*       out  = (float*)d_out;
    const int n = in_sizes[1] / SAMPLE;

    float* Y;
    __nv_bfloat16 *Ahi, *Alo, *w1h, *w1l, *w2h, *w2l, *wlh, *wll;
    cudaGetSymbolAddress((void**)&Y,   g_Y);
    cudaGetSymbolAddress((void**)&Ahi, g_Ahi);
    cudaGetSymbolAddress((void**)&Alo, g_Alo);
    cudaGetSymbolAddress((void**)&w1h, g_W1hi);
    cudaGetSymbolAddress((void**)&w1l, g_W1lo);
    cudaGetSymbolAddress((void**)&w2h, g_W2hi);
    cudaGetSymbolAddress((void**)&w2l, g_W2lo);
    cudaGetSymbolAddress((void**)&wlh, g_WLhi);
    cudaGetSymbolAddress((void**)&wll, g_WLlo);

    const int SM128 = RS * (2 * 64 + 2 * 128);   // 104448
    const int SM64  = RS * (2 * 64 + 2 * 64);    //  69632
    cudaFuncSetAttribute(gemm_first_kernel,
                         cudaFuncAttributeMaxDynamicSharedMemorySize, SM128);
    cudaFuncSetAttribute(gemm_mid_kernel<128, 128>,
                         cudaFuncAttributeMaxDynamicSharedMemorySize, SM128);
    cudaFuncSetAttribute(gemm_mid_kernel<64, 40>,
                         cudaFuncAttributeMaxDynamicSharedMemorySize, SM64);

    const int gg = (n + 63) / 64;
    const int ag = (n + 7) / 8;

    split_w_kernel<<<160, 256>>>(W1, W2, WL, w1h, w1l, w2h, w2l, wlh, wll);
    gemm_first_kernel<<<gg, 256, SM128>>>(X, w1h, w1l, Y, n);
    gather_split_kernel<<<ag, 256>>>(Y, nbrs, Ahi, Alo, n);
    gemm_mid_kernel<128, 128><<<gg, 256, SM128>>>(Ahi, Alo, w2h, w2l, Y, n);
    gather_split_kernel<<<ag, 256>>>(Y, nbrs, Ahi, Alo, n);
    gemm_mid_kernel<64, 40><<<gg, 256, SM64>>>(Ahi, Alo, wlh, wll, out, n);
}

// round 7
// speedup vs baseline: 1.0458x; 1.0140x over previous
#include <cuda_runtime.h>
#include <cuda_bf16.h>
#include <cstdint>

// ================================================================
// AutoGNN, 7 launches:
//   1) split_w:  W1/W2/WL -> bf16 hi/lo (WL padded 40->64 rows)
//   2) split_x:  X -> (Xhi,Xlo)
//   3) gemm:     Y = (Xhi+Xlo) @ W1^T     [persistent, cp.async pipelined]
//   4) gather:   (Ahi,Alo) = split(relu(mean(Y[nbrs])))
//   5) gemm:     Y = (Ahi+Alo) @ W2^T
//   6) gather
//   7) gemm<64,40>: out = (Ahi+Alo) @ WL^T
// GEMM: 152 persistent CTAs, W resident in smem, A double-buffered
// via cp.async (load of tile t+1 overlaps HMMA of tile t).
// mma.sync m16n8k16 bf16, 3-term hi/lo split, fp32 accum.
// ================================================================

#define FEAT 128
#define SAMPLE 25
#define CLASSES 40
#define MAXN 100000
#define RS 272   // smem row stride bytes (136 bf16): conflict-free ldmatrix
#define NGEMM_CTAS 152

__device__ float         g_Y  [(size_t)MAXN * FEAT];
__device__ __nv_bfloat16 g_Ahi[(size_t)MAXN * FEAT];
__device__ __nv_bfloat16 g_Alo[(size_t)MAXN * FEAT];
__device__ __nv_bfloat16 g_Xhi[(size_t)MAXN * FEAT];
__device__ __nv_bfloat16 g_Xlo[(size_t)MAXN * FEAT];
__device__ __nv_bfloat16 g_W1hi[128 * 128], g_W1lo[128 * 128];
__device__ __nv_bfloat16 g_W2hi[128 * 128], g_W2lo[128 * 128];
__device__ __nv_bfloat16 g_WLhi[64 * 128],  g_WLlo[64 * 128];

__device__ __forceinline__ uint32_t smem_u32(const void* p) {
    uint32_t a;
    asm("{ .reg .u64 t; cvta.to.shared.u64 t, %1; cvt.u32.u64 %0, t; }" : "=r"(a) : "l"(p));
    return a;
}
__device__ __forceinline__ void ldsm4(uint32_t addr, uint32_t& r0, uint32_t& r1,
                                      uint32_t& r2, uint32_t& r3) {
    asm volatile("ldmatrix.sync.aligned.m8n8.x4.shared.b16 {%0,%1,%2,%3}, [%4];"
                 : "=r"(r0), "=r"(r1), "=r"(r2), "=r"(r3) : "r"(addr));
}
__device__ __forceinline__ void mma_bf16(float* c, const uint32_t* a,
                                         uint32_t b0, uint32_t b1) {
    asm volatile(
        "mma.sync.aligned.m16n8k16.row.col.f32.bf16.bf16.f32 "
        "{%0,%1,%2,%3}, {%4,%5,%6,%7}, {%8,%9}, {%0,%1,%2,%3};"
        : "+f"(c[0]), "+f"(c[1]), "+f"(c[2]), "+f"(c[3])
        : "r"(a[0]), "r"(a[1]), "r"(a[2]), "r"(a[3]), "r"(b0), "r"(b1));
}
__device__ __forceinline__ void cp_async16(uint32_t saddr, const void* gaddr,
                                           uint32_t src_sz) {
    asm volatile("cp.async.cg.shared.global [%0], [%1], 16, %2;"
                 :: "r"(saddr), "l"(gaddr), "r"(src_sz));
}
#define CP_COMMIT() asm volatile("cp.async.commit_group;" ::: "memory")
#define CP_WAIT1()  asm volatile("cp.async.wait_group 1;" ::: "memory")

// ================================================================
// Persistent pipelined GEMM: C[t*128.., CST] = (Ahi+Alo) @ (Whi+Wlo)^T
// smem: [Whi NOUT*RS][Wlo NOUT*RS][buf0: Ahi 128*RS, Alo 128*RS][buf1: ...]
// ================================================================
template<int NOUT, int CST>
__global__ __launch_bounds__(512, 1) void gemm_pipe_kernel(
    const __nv_bfloat16* __restrict__ Ahi, const __nv_bfloat16* __restrict__ Alo,
    const __nv_bfloat16* __restrict__ Whi, const __nv_bfloat16* __restrict__ Wlo,
    float* __restrict__ C, int n)
{
    extern __shared__ char smem[];
    constexpr int OFF_WLO = NOUT * RS;
    constexpr int OFF_A0  = 2 * NOUT * RS;
    constexpr int ABUF    = 2 * 128 * RS;      // hi+lo per buffer
    constexpr int WN = NOUT / 4;               // warp n-extent (32 or 16)
    constexpr int NT = WN / 8;                 // n8 tiles per warp (4 or 2)

    const int tid  = threadIdx.x;
    const int wid  = tid >> 5;
    const int lane = tid & 31;
    const int wm   = wid >> 2;                 // 0..3 -> m = wm*32
    const int wn   = wid & 3;                  // 0..3 -> n = wn*WN
    const uint32_t sb = smem_u32(smem);

    // ---- W resident load (once) ----
    #pragma unroll
    for (int i = 0; i < NOUT / 32; i++) {
        int t = i * 512 + tid;
        int row = t >> 4;
        int c16 = t & 15;
        size_t g = (size_t)row * 128 + c16 * 8;
        int off = row * RS + c16 * 16;
        *reinterpret_cast<uint4*>(smem + off) =
            *reinterpret_cast<const uint4*>(Whi + g);
        *reinterpret_cast<uint4*>(smem + OFF_WLO + off) =
            *reinterpret_cast<const uint4*>(Wlo + g);
    }

    const int tiles  = (n + 127) >> 7;
    const int stride = gridDim.x;

    // ---- A tile prefetch (cp.async, zfill OOB rows) ----
    auto prefetch = [&](int t, int buf) {
        const uint32_t abase = sb + OFF_A0 + buf * ABUF;
        const int m0 = t << 7;
        #pragma unroll
        for (int i = 0; i < 4; i++) {
            int k = i * 512 + tid;             // 2048: row 0..127, c16 0..15
            int row = k >> 4;
            int c16 = k & 15;
            int grow = m0 + row;
            uint32_t sz = (grow < n) ? 16u : 0u;
            int gc = (grow < n) ? grow : 0;
            size_t g = (size_t)gc * 128 + c16 * 8;
            uint32_t off = (uint32_t)(row * RS + c16 * 16);
            cp_async16(abase + off,             Ahi + g, sz);
            cp_async16(abase + 128 * RS + off,  Alo + g, sz);
        }
    };

    // lane-derived ldmatrix offsets
    const int l15   = lane & 15;
    const int aHalf = (lane & 16) ? 16 : 0;
    const uint32_t aRowOff0 = (uint32_t)((wm * 32 + l15) * RS + aHalf);
    const uint32_t aRowOff1 = aRowOff0 + 16 * RS;
    const int bRow  = (lane & 7) + ((lane & 16) ? 8 : 0);
    const int bHalf = (lane & 8) ? 16 : 0;
    uint32_t bRowByte[NT / 2];
    #pragma unroll
    for (int jp = 0; jp < NT / 2; jp++)
        bRowByte[jp] = (uint32_t)((wn * WN + jp * 16 + bRow) * RS + bHalf);

    int t0 = blockIdx.x;
    if (t0 < tiles) prefetch(t0, 0);
    CP_COMMIT();

    int it = 0;
    for (int t = t0; t < tiles; t += stride, it++) {
        const int buf = it & 1;
        // issue prefetch of next tile into the other buffer
        int tn = t + stride;
        if (tn < tiles) prefetch(tn, buf ^ 1);
        CP_COMMIT();
        CP_WAIT1();
        __syncthreads();

        const uint32_t aOff = sb + OFF_A0 + buf * ABUF;
        const uint32_t aBase[3] = { aOff, aOff, aOff + 128 * RS };
        const uint32_t wBase[3] = { sb, sb + OFF_WLO, sb };

        float c[2][NT][4];
        #pragma unroll
        for (int mt = 0; mt < 2; mt++)
            #pragma unroll
            for (int j = 0; j < NT; j++)
                #pragma unroll
                for (int q = 0; q < 4; q++) c[mt][j][q] = 0.f;

        #pragma unroll
        for (int s = 0; s < 3; s++) {
            #pragma unroll
            for (int ks = 0; ks < 8; ks++) {
                const uint32_t kb = ks * 32;
                uint32_t a[2][4];
                ldsm4(aBase[s] + aRowOff0 + kb, a[0][0], a[0][1], a[0][2], a[0][3]);
                ldsm4(aBase[s] + aRowOff1 + kb, a[1][0], a[1][1], a[1][2], a[1][3]);
                uint32_t b[NT][2];
                #pragma unroll
                for (int jp = 0; jp < NT / 2; jp++)
                    ldsm4(wBase[s] + bRowByte[jp] + kb,
                          b[2 * jp][0], b[2 * jp][1], b[2 * jp + 1][0], b[2 * jp + 1][1]);
                #pragma unroll
                for (int mt = 0; mt < 2; mt++)
                    #pragma unroll
                    for (int j = 0; j < NT; j++)
                        mma_bf16(c[mt][j], a[mt], b[j][0], b[j][1]);
            }
        }

        // epilogue
        const int m0 = t << 7;
        const int qrow = lane >> 2;
        const int qcol = (lane & 3) * 2;
        #pragma unroll
        for (int mt = 0; mt < 2; mt++) {
            #pragma unroll
            for (int half = 0; half < 2; half++) {
                int m_g = m0 + wm * 32 + mt * 16 + qrow + half * 8;
                if (m_g < n) {
                    float* crow = C + (size_t)m_g * CST;
                    #pragma unroll
                    for (int j = 0; j < NT; j++) {
                        int n_g = wn * WN + j * 8 + qcol;
                        if (CST == 128 || n_g < CST) {
                            float2 v = make_float2(c[mt][j][half * 2],
                                                   c[mt][j][half * 2 + 1]);
                            *reinterpret_cast<float2*>(crow + n_g) = v;
                        }
                    }
                }
            }
        }
        __syncthreads();   // all reads of buf done before it is refilled next iter
    }
}

// ---------------- gather + split (high occupancy) ---------------------------
__global__ __launch_bounds__(256) void gather_split_kernel(
    const float* __restrict__ Y, const int* __restrict__ nbrs,
    __nv_bfloat16* __restrict__ Hhi, __nv_bfloat16* __restrict__ Hlo, int n)
{
    const int warp = (blockIdx.x * blockDim.x + threadIdx.x) >> 5;
    const int lane = threadIdx.x & 31;
    if (warp >= n) return;

    int idx = 0;
    if (lane < SAMPLE) idx = nbrs[(size_t)warp * SAMPLE + lane];

    float4 acc = make_float4(0.f, 0.f, 0.f, 0.f);
    #pragma unroll
    for (int j = 0; j < SAMPLE; j++) {
        int row = __shfl_sync(0xffffffffu, idx, j);
        float4 v = __ldg(reinterpret_cast<const float4*>(Y + (size_t)row * 128) + lane);
        acc.x += v.x; acc.y += v.y; acc.z += v.z; acc.w += v.w;
    }
    const float s = 1.0f / (float)SAMPLE;
    float o[4] = { fmaxf(acc.x * s, 0.f), fmaxf(acc.y * s, 0.f),
                   fmaxf(acc.z * s, 0.f), fmaxf(acc.w * s, 0.f) };
    __nv_bfloat16 h[4], l[4];
    #pragma unroll
    for (int q = 0; q < 4; q++) {
        h[q] = __float2bfloat16(o[q]);
        l[q] = __float2bfloat16(o[q] - __bfloat162float(h[q]));
    }
    *(reinterpret_cast<uint2*>(Hhi + (size_t)warp * 128) + lane) =
        *reinterpret_cast<uint2*>(h);
    *(reinterpret_cast<uint2*>(Hlo + (size_t)warp * 128) + lane) =
        *reinterpret_cast<uint2*>(l);
}

// ---------------- splitters --------------------------------------------------
__global__ void split_x_kernel(const float* __restrict__ X,
                               __nv_bfloat16* __restrict__ hi,
                               __nv_bfloat16* __restrict__ lo, int total4)
{
    int i = blockIdx.x * blockDim.x + threadIdx.x;
    if (i >= total4) return;
    float4 v = __ldg(reinterpret_cast<const float4*>(X) + i);
    float f[4] = { v.x, v.y, v.z, v.w };
    __nv_bfloat16 h[4], l[4];
    #pragma unroll
    for (int q = 0; q < 4; q++) {
        h[q] = __float2bfloat16(f[q]);
        l[q] = __float2bfloat16(f[q] - __bfloat162float(h[q]));
    }
    *(reinterpret_cast<uint2*>(hi) + i) = *reinterpret_cast<uint2*>(h);
    *(reinterpret_cast<uint2*>(lo) + i) = *reinterpret_cast<uint2*>(l);
}

__global__ void split_w_kernel(const float* __restrict__ W1,
                               const float* __restrict__ W2,
                               const float* __restrict__ WL,
                               __nv_bfloat16* w1h, __nv_bfloat16* w1l,
                               __nv_bfloat16* w2h, __nv_bfloat16* w2l,
                               __nv_bfloat16* wlh, __nv_bfloat16* wll)
{
    int i = blockIdx.x * blockDim.x + threadIdx.x;  // 0 .. 40959
    float v; __nv_bfloat16 *ph, *pl; int idx;
    if (i < 16384)      { v = W1[i];            ph = w1h; pl = w1l; idx = i; }
    else if (i < 32768) { idx = i - 16384; v = W2[idx]; ph = w2h; pl = w2l; }
    else if (i < 40960) {
        idx = i - 32768;                 // padded [64][128]
        int row = idx >> 7;
        v = (row < CLASSES) ? WL[idx] : 0.f;
        ph = wlh; pl = wll;
    } else return;
    __nv_bfloat16 h = __float2bfloat16(v);
    ph[idx] = h;
    pl[idx] = __float2bfloat16(v - __bfloat162float(h));
}

// ================================================================
extern "C" void kernel_launch(void* const* d_in, const int* in_sizes, int n_in,
                              void* d_out, int out_size)
{
    const float* X    = (const float*)d_in[0];
    const int*   nbrs = (const int*)  d_in[1];
    const float* W1   = (const float*)d_in[2];
    const float* W2   = (const float*)d_in[3];
    const float* WL   = (const float*)d_in[4];
    float*       out  = (float*)d_out;
    const int n = in_sizes[1] / SAMPLE;

    float* Y;
    __nv_bfloat16 *Ahi, *Alo, *Xhi, *Xlo, *w1h, *w1l, *w2h, *w2l, *wlh, *wll;
    cudaGetSymbolAddress((void**)&Y,   g_Y);
    cudaGetSymbolAddress((void**)&Ahi, g_Ahi);
    cudaGetSymbolAddress((void**)&Alo, g_Alo);
    cudaGetSymbolAddress((void**)&Xhi, g_Xhi);
    cudaGetSymbolAddress((void**)&Xlo, g_Xlo);
    cudaGetSymbolAddress((void**)&w1h, g_W1hi);
    cudaGetSymbolAddress((void**)&w1l, g_W1lo);
    cudaGetSymbolAddress((void**)&w2h, g_W2hi);
    cudaGetSymbolAddress((void**)&w2l, g_W2lo);
    cudaGetSymbolAddress((void**)&wlh, g_WLhi);
    cudaGetSymbolAddress((void**)&wll, g_WLlo);

    // smem: W (2*NOUT*RS) + 2 A buffers (2*128*RS each)
    const int SM128 = RS * (2 * 128) + 2 * RS * (2 * 128);  // 208896
    const int SM64  = RS * (2 * 64)  + 2 * RS * (2 * 128);  // 174080
    cudaFuncSetAttribute(gemm_pipe_kernel<128, 128>,
                         cudaFuncAttributeMaxDynamicSharedMemorySize, SM128);
    cudaFuncSetAttribute(gemm_pipe_kernel<64, 40>,
                         cudaFuncAttributeMaxDynamicSharedMemorySize, SM64);

    const int sg = (n * 32 + 255) / 256;
    const int ag = (n + 7) / 8;

    split_w_kernel<<<160, 256>>>(W1, W2, WL, w1h, w1l, w2h, w2l, wlh, wll);
    split_x_kernel<<<sg, 256>>>(X, Xhi, Xlo, n * 32);
    gemm_pipe_kernel<128, 128><<<NGEMM_CTAS, 512, SM128>>>(Xhi, Xlo, w1h, w1l, Y, n);
    gather_split_kernel<<<ag, 256>>>(Y, nbrs, Ahi, Alo, n);
    gemm_pipe_kernel<128, 128><<<NGEMM_CTAS, 512, SM128>>>(Ahi, Alo, w2h, w2l, Y, n);
    gather_split_kernel<<<ag, 256>>>(Y, nbrs, Ahi, Alo, n);
    gemm_pipe_kernel<64, 40><<<NGEMM_CTAS, 512, SM64>>>(Ahi, Alo, wlh, wll, out, n);
}